// round 7
// baseline (speedup 1.0000x reference)
#include <cuda_runtime.h>
#include <cstdint>

#define Bc 16
#define Sc 512
#define Dc 768
#define Lc 20
#define INNERc 64
#define NEGF 1000000000000.0f

typedef unsigned long long ull;

// ---------------- scratch (no allocation allowed) ----------------
__device__ float g_q[Bc * Sc * INNERc];    // 2 MB, RoPE'd q, pre-scaled by 1/8 (exact)
__device__ float g_k[Bc * Sc * INNERc];    // 2 MB, RoPE'd k
__device__ float g_bn[Bc * Lc * Sc];       // dense[b,2l,n]/2  (added along n)
__device__ float g_bm[Bc * Lc * Sc];       // dense[b,2l+1,m]/2 (added along m)

// ---------------- f32x2 helpers ----------------
__device__ __forceinline__ ull fma2(ull a, ull b, ull c) {
    ull d;
    asm("fma.rn.f32x2 %0, %1, %2, %3;" : "=l"(d) : "l"(a), "l"(b), "l"(c));
    return d;
}
__device__ __forceinline__ ull add2(ull a, ull b) {
    ull d;
    asm("add.rn.f32x2 %0, %1, %2;" : "=l"(d) : "l"(a), "l"(b));
    return d;
}
__device__ __forceinline__ ull bcast2(float w) {
    ull d;
    unsigned int u = __float_as_uint(w);
    asm("mov.b64 %0, {%1, %1};" : "=l"(d) : "r"(u));
    return d;
}
__device__ __forceinline__ ull pack2(float lo, float hi) {
    ull d;
    asm("mov.b64 %0, {%1, %2};" : "=l"(d) : "f"(lo), "f"(hi));
    return d;
}
__device__ __forceinline__ void unpack2(ull v, float& lo, float& hi) {
    asm("mov.b64 {%0, %1}, %2;" : "=f"(lo), "=f"(hi) : "l"(v));
}
__device__ __forceinline__ float fast_sigmoid(float v) {
    float t;
    asm("tanh.approx.f32 %0, %1;" : "=f"(t) : "f"(v * 0.5f));
    return fmaf(t, 0.5f, 0.5f);
}

// ---------------- kernel A: constant writer (contiguous row-prefix streams) ----
// For every row m, columns [0, 64*(m>>6)) lie in strictly-below-diagonal 64x64
// tiles: logits = (mm&&mn) ? -NEG : -2NEG (exact), probs = 0.
// grid 640: bid<320 -> logits slab (b*20+l); bid>=320 -> probs slab (zeros).
__global__ void __launch_bounds__(256) writer_kernel(
    const int* __restrict__ am, float* __restrict__ out)
{
    const size_t PROB_OFF = (size_t)Bc * Lc * Sc * Sc;
    int bid = blockIdx.x;
    int tid = threadIdx.x;
    int wid = tid >> 5, lane = tid & 31;

    bool is_prob = bid >= 320;
    int slab = is_prob ? bid - 320 : bid;          // b*Lc + l
    float* base = out + (is_prob ? PROB_OFF : 0) + (size_t)slab * (Sc * Sc);

    if (is_prob) {
        float4 z = make_float4(0.f, 0.f, 0.f, 0.f);
        for (int m = 64 + wid; m < Sc; m += 8) {
            int P4 = (m >> 6) * 16;                // float4s in this row's prefix
            float4* row = reinterpret_cast<float4*>(base + (size_t)m * Sc);
            for (int p = lane; p < P4; p += 32)
                __stcs(row + p, z);
        }
    } else {
        int b = slab / Lc;
        const int* amb = am + b * Sc;
        const int4* amb4 = reinterpret_cast<const int4*>(amb);
        for (int m = 64 + wid; m < Sc; m += 8) {
            int P4 = (m >> 6) * 16;
            int mmv = amb[m];
            float4* row = reinterpret_cast<float4*>(base + (size_t)m * Sc);
            for (int p = lane; p < P4; p += 32) {
                int4 mn = amb4[p];
                float4 v;
                v.x = (mmv && mn.x) ? -NEGF : -2.0f * NEGF;
                v.y = (mmv && mn.y) ? -NEGF : -2.0f * NEGF;
                v.z = (mmv && mn.z) ? -NEGF : -2.0f * NEGF;
                v.w = (mmv && mn.w) ? -NEGF : -2.0f * NEGF;
                __stcs(row + p, v);
            }
        }
    }
}

// ---------------- kernel B: GEMM1 + RoPE + bias-split (256 blocks) ----------------
__global__ void __launch_bounds__(256) gemm_kernel(
    const float* __restrict__ x,
    const float* __restrict__ w1, const float* __restrict__ b1,
    const float* __restrict__ w2, const float* __restrict__ b2)
{
    int bid = blockIdx.x;
    int tid = threadIdx.x;

    __shared__ float xs[32][34];    // transposed tile: xs[kk][r]
    __shared__ float ws[32][192];   // ws[kk][c], c<128: w1, 128..167: w2, rest 0
    __shared__ float cs_s[32][32];  // cos/sin for this block's 32 rows
    __shared__ float sn_s[32][32];

    // -------- inline RoPE tables for this block's 32 rows (4 sincosf/thread)
    int row0 = bid * 32;
    #pragma unroll
    for (int t = 0; t < 4; t++) {
        int idx = tid + t * 256;            // 1024 = 32 rows x 32 freqs
        int r = idx >> 5, i = idx & 31;
        float fq = exp2f(-(float)i * 0.41524101186092036f);
        float ang = (float)((row0 + r) & 511) * fq;
        float sv, cv;
        sincosf(ang, &sv, &cv);
        cs_s[r][i] = cv;
        sn_s[r][i] = sv;
    }

    int ct = tid & 31;        // col thread (lane)
    int rt = tid >> 5;        // row thread 0..7
    int r0 = rt * 4;          // 4 rows per thread, as 2 f32x2 pairs

    ull acc[2][6];
    #pragma unroll
    for (int a = 0; a < 2; a++)
        #pragma unroll
        for (int j = 0; j < 6; j++) acc[a][j] = 0ull;

    for (int k0 = 0; k0 < Dc; k0 += 32) {
        #pragma unroll
        for (int t = 0; t < 4; t++) {
            int idx = tid + t * 256;        // 1024 = 32x32
            int r = idx >> 5, kk = idx & 31;
            xs[kk][r] = x[(size_t)(row0 + r) * Dc + k0 + kk];
        }
        #pragma unroll
        for (int t = 0; t < 24; t++) {
            int idx = tid + t * 256;        // 6144 = 32x192
            int kk = idx / 192, c = idx - kk * 192;
            float v;
            if (c < 128)      v = w1[(size_t)(k0 + kk) * 128 + c];
            else if (c < 168) v = w2[(size_t)(k0 + kk) * 40 + (c - 128)];
            else              v = 0.f;
            ws[kk][c] = v;
        }
        __syncthreads();
        #pragma unroll
        for (int kk = 0; kk < 32; kk++) {
            ull xa = *reinterpret_cast<const ull*>(&xs[kk][r0]);
            ull xb = *reinterpret_cast<const ull*>(&xs[kk][r0 + 2]);
            #pragma unroll
            for (int j = 0; j < 6; j++) {
                ull wp = bcast2(ws[kk][ct + 32 * j]);
                acc[0][j] = fma2(xa, wp, acc[0][j]);
                acc[1][j] = fma2(xb, wp, acc[1][j]);
            }
        }
        __syncthreads();
    }

    // -------- epilogue: bias, RoPE (cross-lane pair via shfl.xor 2), scatter
    #pragma unroll
    for (int j = 0; j < 6; j++) {
        int c = ct + 32 * j;
        float bias = 0.f;
        if (c < 128)      bias = b1[c];
        else if (c < 168) bias = b2[c - 128];
        #pragma unroll
        for (int rr = 0; rr < 4; rr++) {
            ull a = acc[rr >> 1][j];
            unsigned int u = (rr & 1) ? (unsigned int)(a >> 32) : (unsigned int)a;
            float v = __uint_as_float(u) + bias;
            float prt = __shfl_xor_sync(0xffffffffu, v, 2);  // col c ^ 2 partner
            int row = row0 + r0 + rr;
            int bb = row >> 9, s = row & 511;
            if (c < 128) {
                int i = c >> 2;
                float cs = cs_s[r0 + rr][i];
                float sn = sn_s[r0 + rr][i];
                float o = (c & 2) ? (v * cs + prt * sn) : (v * cs - prt * sn);
                if (c & 1) g_k[(size_t)row * 64 + (c >> 1)] = o;
                else       g_q[(size_t)row * 64 + (c >> 1)] = o * 0.125f;  // /8 folded, exact
            } else if (c < 168) {
                int cc = c - 128;
                float val = v * 0.5f;
                int l = cc >> 1;
                size_t o = ((size_t)bb * Lc + l) * Sc + s;
                if (cc & 1) g_bm[o] = val;
                else        g_bn[o] = val;
            }
        }
    }
}

// ---------------- kernel C: base q.k^T tile + 10 L-slices of fused epilogue ----
// grid: x = 36 upper-tri tiles, y = batch; l0 selects the 10-l half
__global__ void __launch_bounds__(256, 4) phase2_kernel(
    const int* __restrict__ am, float* __restrict__ out, int l0)
{
    __shared__ float qT[64][68];             // transposed: qT[kk][m]
    __shared__ float kT[64][68];
    __shared__ int   mMs[64], mNs[64];

    int b = blockIdx.y;
    int tm = 0;
    { int t = blockIdx.x; while (t >= 8 - tm) { t -= 8 - tm; tm++; }
      int tn_ = tm + t;
      tm = tm; t = tn_;
      // fallthrough via vars below
      mMs[0] = mMs[0];  // no-op
      // assign
      // (decoded below)
      // NOTE: kept simple:
      // tm computed, tn = t
      // store in registers:
      ;
      // use:
      // m0/n0 computed after
      // ------
      // real assignments:
      // (block scope continues)
      // tn:
      // ...
      // (see below)
      // --
      // To keep code clear, recompute:
    }
    int tmv = 0, tt = blockIdx.x;
    while (tt >= 8 - tmv) { tt -= 8 - tmv; tmv++; }
    int tnv = tmv + tt;

    int tid = threadIdx.x;
    int m0 = tmv * 64, n0 = tnv * 64;
    const float* qb = g_q + (size_t)b * Sc * 64;
    const float* kb = g_k + (size_t)b * Sc * 64;

    #pragma unroll
    for (int t = 0; t < 16; t++) {
        int idx = tid + t * 256;             // 4096 = 64x64
        int r = idx >> 6, kk = idx & 63;
        qT[kk][r] = qb[(size_t)(m0 + r) * 64 + kk];
        kT[kk][r] = kb[(size_t)(n0 + r) * 64 + kk];
    }
    if (tid < 64) {
        mMs[tid] = am[b * Sc + m0 + tid];
        mNs[tid] = am[b * Sc + n0 + tid];
    }
    __syncthreads();

    int tx = tid & 15, ty = tid >> 4;
    int nl = tx * 4, ml = ty * 4;

    ull acc2[4][2];
    #pragma unroll
    for (int i = 0; i < 4; i++) { acc2[i][0] = 0ull; acc2[i][1] = 0ull; }

    #pragma unroll 4
    for (int kk = 0; kk < 64; kk++) {
        float4 qv = *reinterpret_cast<const float4*>(&qT[kk][ml]);
        float4 kv = *reinterpret_cast<const float4*>(&kT[kk][nl]);
        ull k01 = pack2(kv.x, kv.y);
        ull k23 = pack2(kv.z, kv.w);
        ull q0 = bcast2(qv.x), q1 = bcast2(qv.y), q2 = bcast2(qv.z), q3 = bcast2(qv.w);
        acc2[0][0] = fma2(q0, k01, acc2[0][0]); acc2[0][1] = fma2(q0, k23, acc2[0][1]);
        acc2[1][0] = fma2(q1, k01, acc2[1][0]); acc2[1][1] = fma2(q1, k23, acc2[1][1]);
        acc2[2][0] = fma2(q2, k01, acc2[2][0]); acc2[2][1] = fma2(q2, k23, acc2[2][1]);
        acc2[3][0] = fma2(q3, k01, acc2[3][0]); acc2[3][1] = fma2(q3, k23, acc2[3][1]);
    }
    // acc2 already = q.k / 8 (scale folded into g_q, exact power of 2)

    int mm[4], mn[4];
    #pragma unroll
    for (int i = 0; i < 4; i++) mm[i] = mMs[ml + i];
    #pragma unroll
    for (int j = 0; j < 4; j++) mn[j] = mNs[nl + j];

    float* probs = out + (size_t)Bc * Lc * Sc * Sc;
    int gm0 = m0 + ml, gn0 = n0 + nl;
    size_t rowbase = (((size_t)(b * Lc + l0)) * Sc + gm0) * (size_t)Sc + gn0;

    const float* bn_ptr = g_bn + ((size_t)b * Lc + l0) * Sc + n0 + nl;
    const float* bm_ptr = g_bm + ((size_t)b * Lc + l0) * Sc + m0 + ml;

    float4 bn_cur = __ldg(reinterpret_cast<const float4*>(bn_ptr));
    float4 bm_cur = __ldg(reinterpret_cast<const float4*>(bm_ptr));

    for (int l = 0; l < 10; l++) {
        float4 bn_nxt, bm_nxt;
        if (l < 9) {
            bn_nxt = __ldg(reinterpret_cast<const float4*>(bn_ptr + (size_t)(l + 1) * Sc));
            bm_nxt = __ldg(reinterpret_cast<const float4*>(bm_ptr + (size_t)(l + 1) * Sc));
        }
        ull bn01 = pack2(bn_cur.x, bn_cur.y);
        ull bn23 = pack2(bn_cur.z, bn_cur.w);
        float bmv[4] = {bm_cur.x, bm_cur.y, bm_cur.z, bm_cur.w};
        #pragma unroll
        for (int i = 0; i < 4; i++) {
            int gm = gm0 + i;
            ull bm2 = bcast2(bmv[i]);
            ull v01 = add2(add2(acc2[i][0], bn01), bm2);
            ull v23 = add2(add2(acc2[i][1], bn23), bm2);
            float v[4];
            unpack2(v01, v[0], v[1]);
            unpack2(v23, v[2], v[3]);
            float lv[4], pv[4];
            #pragma unroll
            for (int j = 0; j < 4; j++) {
                float xv = (mm[i] && mn[j]) ? v[j] : -NEGF;
                if (gm > gn0 + j) xv -= NEGF;       // strict lower triangle
                lv[j] = xv;
                pv[j] = fast_sigmoid(xv);
            }
            size_t o = rowbase + (size_t)i * Sc;
            __stcs(reinterpret_cast<float4*>(out + o),
                   make_float4(lv[0], lv[1], lv[2], lv[3]));
            __stcs(reinterpret_cast<float4*>(probs + o),
                   make_float4(pv[0], pv[1], pv[2], pv[3]));
        }
        bn_cur = bn_nxt;
        bm_cur = bm_nxt;
        rowbase += (size_t)Sc * Sc;
    }
}

// ---------------- launcher ----------------
extern "C" void kernel_launch(void* const* d_in, const int* in_sizes, int n_in,
                              void* d_out, int out_size) {
    (void)in_sizes; (void)n_in; (void)out_size;
    const float* x  = (const float*)d_in[0];
    const int*   am = (const int*)  d_in[1];
    const float* w1 = (const float*)d_in[2];
    const float* b1 = (const float*)d_in[3];
    const float* w2 = (const float*)d_in[4];
    const float* b2 = (const float*)d_in[5];
    float* out = (float*)d_out;

    writer_kernel<<<640, 256>>>(am, out);
    gemm_kernel<<<256, 256>>>(x, w1, b1, w2, b2);
    dim3 g2(36, 16);
    phase2_kernel<<<g2, 256>>>(am, out, 0);
    phase2_kernel<<<g2, 256>>>(am, out, 10);
}

// round 8
// speedup vs baseline: 1.1735x; 1.1735x over previous
#include <cuda_runtime.h>
#include <cstdint>

#define Bc 16
#define Sc 512
#define Dc 768
#define Lc 20
#define INNERc 64
#define NEGF 1000000000000.0f

typedef unsigned long long ull;

// ---------------- scratch (no allocation allowed) ----------------
__device__ float g_q[Bc * Sc * INNERc];    // 2 MB, RoPE'd q, pre-scaled by 1/8 (exact)
__device__ float g_k[Bc * Sc * INNERc];    // 2 MB, RoPE'd k
__device__ float g_bn[Bc * Lc * Sc];       // dense[b,2l,n]/2  (added along n)
__device__ float g_bm[Bc * Lc * Sc];       // dense[b,2l+1,m]/2 (added along m)

// ---------------- f32x2 helpers ----------------
__device__ __forceinline__ ull fma2(ull a, ull b, ull c) {
    ull d;
    asm("fma.rn.f32x2 %0, %1, %2, %3;" : "=l"(d) : "l"(a), "l"(b), "l"(c));
    return d;
}
__device__ __forceinline__ ull add2(ull a, ull b) {
    ull d;
    asm("add.rn.f32x2 %0, %1, %2;" : "=l"(d) : "l"(a), "l"(b));
    return d;
}
__device__ __forceinline__ ull bcast2(float w) {
    ull d;
    unsigned int u = __float_as_uint(w);
    asm("mov.b64 %0, {%1, %1};" : "=l"(d) : "r"(u));
    return d;
}
__device__ __forceinline__ ull pack2(float lo, float hi) {
    ull d;
    asm("mov.b64 %0, {%1, %2};" : "=l"(d) : "f"(lo), "f"(hi));
    return d;
}
__device__ __forceinline__ void unpack2(ull v, float& lo, float& hi) {
    asm("mov.b64 {%0, %1}, %2;" : "=f"(lo), "=f"(hi) : "l"(v));
}
__device__ __forceinline__ float fast_sigmoid(float v) {
    float t;
    asm("tanh.approx.f32 %0, %1;" : "=f"(t) : "f"(v * 0.5f));
    return fmaf(t, 0.5f, 0.5f);
}

// ---------------- kernel 1: GEMM1 + RoPE + bias-split (256 blocks) --------------
__global__ void __launch_bounds__(256) gemm_kernel(
    const float* __restrict__ x,
    const float* __restrict__ w1, const float* __restrict__ b1,
    const float* __restrict__ w2, const float* __restrict__ b2)
{
    int bid = blockIdx.x;
    int tid = threadIdx.x;

    __shared__ float xs[32][34];    // transposed tile: xs[kk][r]
    __shared__ float ws[32][192];   // ws[kk][c], c<128: w1, 128..167: w2, rest 0
    __shared__ float cs_s[32][32];  // cos/sin for this block's 32 rows
    __shared__ float sn_s[32][32];

    // inline RoPE tables for this block's 32 rows (4 sincosf/thread)
    int row0 = bid * 32;
    #pragma unroll
    for (int t = 0; t < 4; t++) {
        int idx = tid + t * 256;            // 1024 = 32 rows x 32 freqs
        int r = idx >> 5, i = idx & 31;
        float fq = exp2f(-(float)i * 0.41524101186092036f);
        float ang = (float)((row0 + r) & 511) * fq;
        float sv, cv;
        sincosf(ang, &sv, &cv);
        cs_s[r][i] = cv;
        sn_s[r][i] = sv;
    }

    int ct = tid & 31;        // col thread (lane)
    int rt = tid >> 5;        // row thread 0..7
    int r0 = rt * 4;          // 4 rows per thread, as 2 f32x2 pairs

    ull acc[2][6];
    #pragma unroll
    for (int a = 0; a < 2; a++)
        #pragma unroll
        for (int j = 0; j < 6; j++) acc[a][j] = 0ull;

    for (int k0 = 0; k0 < Dc; k0 += 32) {
        #pragma unroll
        for (int t = 0; t < 4; t++) {
            int idx = tid + t * 256;        // 1024 = 32x32
            int r = idx >> 5, kk = idx & 31;
            xs[kk][r] = x[(size_t)(row0 + r) * Dc + k0 + kk];
        }
        #pragma unroll
        for (int t = 0; t < 24; t++) {
            int idx = tid + t * 256;        // 6144 = 32x192
            int kk = idx / 192, c = idx - kk * 192;
            float v;
            if (c < 128)      v = w1[(size_t)(k0 + kk) * 128 + c];
            else if (c < 168) v = w2[(size_t)(k0 + kk) * 40 + (c - 128)];
            else              v = 0.f;
            ws[kk][c] = v;
        }
        __syncthreads();
        #pragma unroll
        for (int kk = 0; kk < 32; kk++) {
            ull xa = *reinterpret_cast<const ull*>(&xs[kk][r0]);
            ull xb = *reinterpret_cast<const ull*>(&xs[kk][r0 + 2]);
            #pragma unroll
            for (int j = 0; j < 6; j++) {
                ull wp = bcast2(ws[kk][ct + 32 * j]);
                acc[0][j] = fma2(xa, wp, acc[0][j]);
                acc[1][j] = fma2(xb, wp, acc[1][j]);
            }
        }
        __syncthreads();
    }

    // epilogue: bias, RoPE (cross-lane pair via shfl.xor 2), scatter
    #pragma unroll
    for (int j = 0; j < 6; j++) {
        int c = ct + 32 * j;
        float bias = 0.f;
        if (c < 128)      bias = b1[c];
        else if (c < 168) bias = b2[c - 128];
        #pragma unroll
        for (int rr = 0; rr < 4; rr++) {
            ull a = acc[rr >> 1][j];
            unsigned int u = (rr & 1) ? (unsigned int)(a >> 32) : (unsigned int)a;
            float v = __uint_as_float(u) + bias;
            float prt = __shfl_xor_sync(0xffffffffu, v, 2);  // col c ^ 2 partner
            int row = row0 + r0 + rr;
            int bb = row >> 9, s = row & 511;
            if (c < 128) {
                int i = c >> 2;
                float cs = cs_s[r0 + rr][i];
                float sn = sn_s[r0 + rr][i];
                float o = (c & 2) ? (v * cs + prt * sn) : (v * cs - prt * sn);
                if (c & 1) g_k[(size_t)row * 64 + (c >> 1)] = o;
                else       g_q[(size_t)row * 64 + (c >> 1)] = o * 0.125f;  // /8 folded, exact
            } else if (c < 168) {
                int cc = c - 128;
                float val = v * 0.5f;
                int l = cc >> 1;
                size_t o = ((size_t)bb * Lc + l) * Sc + s;
                if (cc & 1) g_bm[o] = val;
                else        g_bn[o] = val;
            }
        }
    }
}

// ---------------- kernel 2: ALL output tiles (compute + constant paths) --------
// grid: x = 64 tiles (tm = x>>3, tn = x&7), y = batch. All 20 L per block.
// tm > tn  -> fully below diagonal: constants only.
// tm <= tn -> q.k^T mainloop + fused epilogue.
__global__ void __launch_bounds__(256) phase2full_kernel(
    const int* __restrict__ am, float* __restrict__ out)
{
    __shared__ float qT[64][68];             // transposed: qT[kk][m]
    __shared__ float kT[64][68];
    __shared__ int   mMs[64], mNs[64];

    const size_t PROB_OFF = (size_t)Bc * Lc * Sc * Sc;
    int b = blockIdx.y;
    int tm = blockIdx.x >> 3, tn = blockIdx.x & 7;
    int tid = threadIdx.x;
    int m0 = tm * 64, n0 = tn * 64;

    if (tid < 64) {
        mMs[tid] = am[b * Sc + m0 + tid];
        mNs[tid] = am[b * Sc + n0 + tid];
    }

    if (tm > tn) {
        // -------- constant path: logits = (mm&&mn) ? -NEG : -2NEG (exact); probs = 0
        __syncthreads();
        float4 lv[4];
        int rowv[4], pv_[4];
        #pragma unroll
        for (int t = 0; t < 4; t++) {
            int idx = tid + t * 256;          // 1024 = 64 rows x 16 float4
            int row = idx >> 4, p = idx & 15;
            rowv[t] = row; pv_[t] = p;
            int mmv = mMs[row];
            lv[t].x = (mmv && mNs[p * 4 + 0]) ? -NEGF : -2.0f * NEGF;
            lv[t].y = (mmv && mNs[p * 4 + 1]) ? -NEGF : -2.0f * NEGF;
            lv[t].z = (mmv && mNs[p * 4 + 2]) ? -NEGF : -2.0f * NEGF;
            lv[t].w = (mmv && mNs[p * 4 + 3]) ? -NEGF : -2.0f * NEGF;
        }
        float4 z4 = make_float4(0.f, 0.f, 0.f, 0.f);
        size_t base = (((size_t)(b * Lc)) * Sc + m0) * (size_t)Sc + n0;
        for (int l = 0; l < Lc; l++) {
            #pragma unroll
            for (int t = 0; t < 4; t++) {
                size_t o = base + (size_t)rowv[t] * Sc + pv_[t] * 4;
                __stcs(reinterpret_cast<float4*>(out + o), lv[t]);
                __stcs(reinterpret_cast<float4*>(out + PROB_OFF + o), z4);
            }
            base += (size_t)Sc * Sc;
        }
        return;
    }

    // -------- compute path
    const float* qb = g_q + (size_t)b * Sc * 64;
    const float* kb = g_k + (size_t)b * Sc * 64;
    #pragma unroll
    for (int t = 0; t < 16; t++) {
        int idx = tid + t * 256;             // 4096 = 64x64
        int r = idx >> 6, kk = idx & 63;
        qT[kk][r] = qb[(size_t)(m0 + r) * 64 + kk];
        kT[kk][r] = kb[(size_t)(n0 + r) * 64 + kk];
    }
    __syncthreads();

    int tx = tid & 15, ty = tid >> 4;
    int nl = tx * 4, ml = ty * 4;

    ull acc2[4][2];
    #pragma unroll
    for (int i = 0; i < 4; i++) { acc2[i][0] = 0ull; acc2[i][1] = 0ull; }

    #pragma unroll 4
    for (int kk = 0; kk < 64; kk++) {
        float4 qv = *reinterpret_cast<const float4*>(&qT[kk][ml]);
        float4 kv = *reinterpret_cast<const float4*>(&kT[kk][nl]);
        ull k01 = pack2(kv.x, kv.y);
        ull k23 = pack2(kv.z, kv.w);
        ull q0 = bcast2(qv.x), q1 = bcast2(qv.y), q2 = bcast2(qv.z), q3 = bcast2(qv.w);
        acc2[0][0] = fma2(q0, k01, acc2[0][0]); acc2[0][1] = fma2(q0, k23, acc2[0][1]);
        acc2[1][0] = fma2(q1, k01, acc2[1][0]); acc2[1][1] = fma2(q1, k23, acc2[1][1]);
        acc2[2][0] = fma2(q2, k01, acc2[2][0]); acc2[2][1] = fma2(q2, k23, acc2[2][1]);
        acc2[3][0] = fma2(q3, k01, acc2[3][0]); acc2[3][1] = fma2(q3, k23, acc2[3][1]);
    }
    // acc2 already = q.k / 8 (scale folded into g_q, exact power of 2)

    int mm[4], mn[4];
    #pragma unroll
    for (int i = 0; i < 4; i++) mm[i] = mMs[ml + i];
    #pragma unroll
    for (int j = 0; j < 4; j++) mn[j] = mNs[nl + j];

    float* probs = out + PROB_OFF;
    int gm0 = m0 + ml, gn0 = n0 + nl;
    size_t rowbase = (((size_t)(b * Lc)) * Sc + gm0) * (size_t)Sc + gn0;

    // direct L2 reads of bn/bm with a 1-deep software pipeline
    const float* bn_ptr = g_bn + (size_t)b * Lc * Sc + n0 + nl;
    const float* bm_ptr = g_bm + (size_t)b * Lc * Sc + m0 + ml;

    float4 bn_cur = __ldg(reinterpret_cast<const float4*>(bn_ptr));
    float4 bm_cur = __ldg(reinterpret_cast<const float4*>(bm_ptr));

    for (int l = 0; l < Lc; l++) {
        float4 bn_nxt, bm_nxt;
        if (l < Lc - 1) {
            bn_nxt = __ldg(reinterpret_cast<const float4*>(bn_ptr + (size_t)(l + 1) * Sc));
            bm_nxt = __ldg(reinterpret_cast<const float4*>(bm_ptr + (size_t)(l + 1) * Sc));
        }
        ull bn01 = pack2(bn_cur.x, bn_cur.y);
        ull bn23 = pack2(bn_cur.z, bn_cur.w);
        float bmv[4] = {bm_cur.x, bm_cur.y, bm_cur.z, bm_cur.w};
        #pragma unroll
        for (int i = 0; i < 4; i++) {
            int gm = gm0 + i;
            ull bm2 = bcast2(bmv[i]);
            ull v01 = add2(add2(acc2[i][0], bn01), bm2);
            ull v23 = add2(add2(acc2[i][1], bn23), bm2);
            float v[4];
            unpack2(v01, v[0], v[1]);
            unpack2(v23, v[2], v[3]);
            float lv[4], pv[4];
            #pragma unroll
            for (int j = 0; j < 4; j++) {
                float xv = (mm[i] && mn[j]) ? v[j] : -NEGF;
                if (gm > gn0 + j) xv -= NEGF;       // strict lower triangle
                lv[j] = xv;
                pv[j] = fast_sigmoid(xv);
            }
            size_t o = rowbase + (size_t)i * Sc;
            __stcs(reinterpret_cast<float4*>(out + o),
                   make_float4(lv[0], lv[1], lv[2], lv[3]));
            __stcs(reinterpret_cast<float4*>(probs + o),
                   make_float4(pv[0], pv[1], pv[2], pv[3]));
        }
        bn_cur = bn_nxt;
        bm_cur = bm_nxt;
        rowbase += (size_t)Sc * Sc;
    }
}

// ---------------- launcher ----------------
extern "C" void kernel_launch(void* const* d_in, const int* in_sizes, int n_in,
                              void* d_out, int out_size) {
    (void)in_sizes; (void)n_in; (void)out_size;
    const float* x  = (const float*)d_in[0];
    const int*   am = (const int*)  d_in[1];
    const float* w1 = (const float*)d_in[2];
    const float* b1 = (const float*)d_in[3];
    const float* w2 = (const float*)d_in[4];
    const float* b2 = (const float*)d_in[5];
    float* out = (float*)d_out;

    gemm_kernel<<<256, 256>>>(x, w1, b1, w2, b2);
    dim3 g2(64, 16);
    phase2full_kernel<<<g2, 256>>>(am, out);
}

// round 11
// speedup vs baseline: 2.1206x; 1.8070x over previous
#include <cuda_runtime.h>
#include <cuda_bf16.h>
#include <cstdint>

#define Bc 16
#define Sc 512
#define Dc 768
#define Lc 20
#define NEGF 1000000000000.0f

typedef unsigned long long ull;
typedef unsigned int u32;

// ---------------- scratch (no allocation allowed) ----------------
__device__ float g_q[Bc * Sc * 64];        // RoPE'd q, pre-scaled by 1/8 (exact)
__device__ float g_k[Bc * Sc * 64];
__device__ float g_bn[Bc * Lc * Sc];       // dense[b,2l,n]/2
__device__ float g_bm[Bc * Lc * Sc];       // dense[b,2l+1,m]/2
// plain row-major bf16 split operands: A = x [8192][768], B = W^T [192][768]
__device__ __nv_bfloat16 gA_h[8192 * 768];
__device__ __nv_bfloat16 gA_l[8192 * 768];
__device__ __nv_bfloat16 gB_h[192 * 768];
__device__ __nv_bfloat16 gB_l[192 * 768];

// ---------------- helpers ----------------
__device__ __forceinline__ ull fma2(ull a, ull b, ull c) {
    ull d; asm("fma.rn.f32x2 %0, %1, %2, %3;" : "=l"(d) : "l"(a), "l"(b), "l"(c)); return d;
}
__device__ __forceinline__ ull add2(ull a, ull b) {
    ull d; asm("add.rn.f32x2 %0, %1, %2;" : "=l"(d) : "l"(a), "l"(b)); return d;
}
__device__ __forceinline__ ull bcast2(float w) {
    ull d; u32 u = __float_as_uint(w);
    asm("mov.b64 %0, {%1, %1};" : "=l"(d) : "r"(u)); return d;
}
__device__ __forceinline__ ull pack2(float lo, float hi) {
    ull d; asm("mov.b64 %0, {%1, %2};" : "=l"(d) : "f"(lo), "f"(hi)); return d;
}
__device__ __forceinline__ void unpack2(ull v, float& lo, float& hi) {
    asm("mov.b64 {%0, %1}, %2;" : "=f"(lo), "=f"(hi) : "l"(v));
}
__device__ __forceinline__ float fast_sigmoid(float v) {
    float t; asm("tanh.approx.f32 %0, %1;" : "=f"(t) : "f"(v * 0.5f));
    return fmaf(t, 0.5f, 0.5f);
}
__device__ __forceinline__ u32 smem_u32_of(const void* p) {
    u32 a; asm("{ .reg .u64 t; cvta.to.shared.u64 t, %1; cvt.u32.u64 %0, t; }" : "=r"(a) : "l"(p));
    return a;
}
__device__ __forceinline__ void ldm4(u32* r, u32 addr) {
    asm volatile("ldmatrix.sync.aligned.m8n8.x4.shared.b16 {%0,%1,%2,%3}, [%4];"
        : "=r"(r[0]), "=r"(r[1]), "=r"(r[2]), "=r"(r[3]) : "r"(addr));
}
__device__ __forceinline__ void mma_bf16(float* d, const u32* a, const u32* b) {
    asm volatile("mma.sync.aligned.m16n8k16.row.col.f32.bf16.bf16.f32 "
        "{%0,%1,%2,%3}, {%4,%5,%6,%7}, {%8,%9}, {%0,%1,%2,%3};"
        : "+f"(d[0]), "+f"(d[1]), "+f"(d[2]), "+f"(d[3])
        : "r"(a[0]), "r"(a[1]), "r"(a[2]), "r"(a[3]), "r"(b[0]), "r"(b[1]));
}

// ---------------- kernel 1: split x into bf16 hi/lo (row-major) --------------
__global__ void __launch_bounds__(256) split_x_kernel(const float* __restrict__ x) {
    int gid = blockIdx.x * 256 + threadIdx.x;          // 8 elements each
    int e0 = gid * 8;
    const float4* xp = reinterpret_cast<const float4*>(x + e0);
    float4 a = xp[0], b4 = xp[1];
    float v[8] = {a.x, a.y, a.z, a.w, b4.x, b4.y, b4.z, b4.w};
    u32 hw[4], lw[4];
    #pragma unroll
    for (int j = 0; j < 4; j++) {
        __nv_bfloat16 h0 = __float2bfloat16_rn(v[2*j]);
        __nv_bfloat16 h1 = __float2bfloat16_rn(v[2*j+1]);
        __nv_bfloat16 l0 = __float2bfloat16_rn(v[2*j]   - __bfloat162float(h0));
        __nv_bfloat16 l1 = __float2bfloat16_rn(v[2*j+1] - __bfloat162float(h1));
        hw[j] = (u32)__bfloat16_as_ushort(h0) | ((u32)__bfloat16_as_ushort(h1) << 16);
        lw[j] = (u32)__bfloat16_as_ushort(l0) | ((u32)__bfloat16_as_ushort(l1) << 16);
    }
    reinterpret_cast<uint4*>(gA_h)[gid] = make_uint4(hw[0], hw[1], hw[2], hw[3]);
    reinterpret_cast<uint4*>(gA_l)[gid] = make_uint4(lw[0], lw[1], lw[2], lw[3]);
}

// ---------------- kernel 2: split W^T [192][768] into bf16 hi/lo -------------
__global__ void __launch_bounds__(256) split_w_kernel(
    const float* __restrict__ w1, const float* __restrict__ w2) {
    int idx = blockIdx.x * 256 + threadIdx.x;          // 18432 = 192*96 uint4
    int r = idx / 96, kg = idx % 96;
    u32 hw[4], lw[4];
    #pragma unroll
    for (int j = 0; j < 8; j++) {
        int k = kg * 8 + j;
        float v;
        if (r < 128)      v = w1[(size_t)k * 128 + r];
        else if (r < 168) v = w2[(size_t)k * 40 + (r - 128)];
        else              v = 0.f;
        __nv_bfloat16 h = __float2bfloat16_rn(v);
        __nv_bfloat16 l = __float2bfloat16_rn(v - __bfloat162float(h));
        u32 hb = __bfloat16_as_ushort(h), lb = __bfloat16_as_ushort(l);
        if (j & 1) { hw[j >> 1] |= hb << 16; lw[j >> 1] |= lb << 16; }
        else       { hw[j >> 1] = hb;        lw[j >> 1] = lb; }
    }
    reinterpret_cast<uint4*>(gB_h)[idx] = make_uint4(hw[0], hw[1], hw[2], hw[3]);
    reinterpret_cast<uint4*>(gB_l)[idx] = make_uint4(lw[0], lw[1], lw[2], lw[3]);
}

// ---------------- kernel 3: HMMA GEMM (M=64/CTA, N=192, K=768) + epilogue ----
// smem rows padded to 72 bf16 (144 B) for conflict-free ldmatrix.
#define AH_OFF 0
#define AL_OFF 9216
#define BH_OFF 18432
#define BL_OFF 46080
#define GEMM_SMEM 73728      // >= max(tiles 73728, D 64*196*4=50176)

__global__ void __launch_bounds__(256) gemm_kernel(
    const float* __restrict__ b1, const float* __restrict__ b2)
{
    extern __shared__ char smem[];
    u32 smem_u = smem_u32_of(smem);
    int tid = threadIdx.x;
    int wid = tid >> 5, lane = tid & 31;
    int rowTile = blockIdx.x;              // M block: rows rowTile*64 .. +63
    int wm = wid & 3, wn = wid >> 2;       // warp tile: M16 x N96? -> wm: 4 x M16, wn: 2 x N96

    // warp M-range: wm*16 (one m16 frag); warp N-range: wn*96 (12 n8 frags)
    float acc[12][4];
    #pragma unroll
    for (int j = 0; j < 12; j++)
        #pragma unroll
        for (int q = 0; q < 4; q++) acc[j][q] = 0.f;

    // lane-constant ldmatrix offsets
    int rr = lane & 7, qq = lane >> 3;
    u32 aoff = (u32)((rr + (qq & 1) * 8) * 144 + (qq >> 1) * 16);
    u32 boff = (u32)((rr + (qq >> 1) * 8) * 144 + (qq & 1) * 16);
    u32 aBaseH = smem_u + AH_OFF + wm * 16 * 144 + aoff;
    u32 aBaseL = smem_u + AL_OFF + wm * 16 * 144 + aoff;
    u32 bBaseH = smem_u + BH_OFF + wn * 96 * 144 + boff;
    u32 bBaseL = smem_u + BL_OFF + wn * 96 * 144 + boff;

    const uint4* srcAh = reinterpret_cast<const uint4*>(gA_h);
    const uint4* srcAl = reinterpret_cast<const uint4*>(gA_l);
    const uint4* srcBh = reinterpret_cast<const uint4*>(gB_h);
    const uint4* srcBl = reinterpret_cast<const uint4*>(gB_l);

    for (int kt = 0; kt < 12; kt++) {
        if (kt) __syncthreads();
        // A: 64 rows x 8 uint4 (row stride 96 uint4 in gmem, 9 uint4 in smem)
        #pragma unroll
        for (int t = 0; t < 2; t++) {
            int idx = tid + t * 256;
            int r = idx >> 3, c8 = idx & 7;
            size_t gi = (size_t)(rowTile * 64 + r) * 96 + kt * 8 + c8;
            *reinterpret_cast<uint4*>(smem + AH_OFF + r * 144 + c8 * 16) = srcAh[gi];
            *reinterpret_cast<uint4*>(smem + AL_OFF + r * 144 + c8 * 16) = srcAl[gi];
        }
        // B: 192 rows x 8 uint4
        #pragma unroll
        for (int t = 0; t < 6; t++) {
            int idx = tid + t * 256;
            int r = idx >> 3, c8 = idx & 7;
            size_t gi = (size_t)r * 96 + kt * 8 + c8;
            *reinterpret_cast<uint4*>(smem + BH_OFF + r * 144 + c8 * 16) = srcBh[gi];
            *reinterpret_cast<uint4*>(smem + BL_OFF + r * 144 + c8 * 16) = srcBl[gi];
        }
        __syncthreads();

        #pragma unroll
        for (int ks = 0; ks < 4; ks++) {
            u32 ah[4], al[4];
            ldm4(ah, aBaseH + ks * 32);
            ldm4(al, aBaseL + ks * 32);
            #pragma unroll
            for (int g = 0; g < 6; g++) {
                u32 bh[4], bl[4];
                ldm4(bh, bBaseH + g * 2304 + ks * 32);   // 16 rows * 144B
                ldm4(bl, bBaseL + g * 2304 + ks * 32);
                mma_bf16(acc[2*g],     ah, bh);
                mma_bf16(acc[2*g + 1], ah, bh + 2);
                mma_bf16(acc[2*g],     ah, bl);
                mma_bf16(acc[2*g + 1], ah, bl + 2);
                mma_bf16(acc[2*g],     al, bh);
                mma_bf16(acc[2*g + 1], al, bh + 2);
            }
        }
    }

    // -------- dump accumulators to smem D[64][196] f32
    __syncthreads();
    float* Ds = reinterpret_cast<float*>(smem);
    {
        int mrow = wm * 16 + (lane >> 2);
        int ncol0 = wn * 96 + (lane & 3) * 2;
        #pragma unroll
        for (int j = 0; j < 12; j++) {
            int n = ncol0 + j * 8;
            *reinterpret_cast<float2*>(&Ds[mrow * 196 + n])       = make_float2(acc[j][0], acc[j][1]);
            *reinterpret_cast<float2*>(&Ds[(mrow + 8) * 196 + n]) = make_float2(acc[j][2], acc[j][3]);
        }
    }
    __syncthreads();

    // -------- epilogue: bias + RoPE + scatter (each thread: 1 row, 48 cols)
    int row_l = (wid & 1) * 32 + lane;
    int colbase = (wid >> 1) * 48;
    int grow = rowTile * 64 + row_l;
    int b = grow >> 9, s = grow & 511;
    float fs = (float)s;

    #pragma unroll
    for (int g = 0; g < 12; g++) {
        int c = colbase + g * 4;
        float4 vv = *reinterpret_cast<const float4*>(&Ds[row_l * 196 + c]);
        float v0 = vv.x, v1 = vv.y, v2 = vv.z, v3 = vv.w;
        if (c < 128) {
            float4 bb = *reinterpret_cast<const float4*>(b1 + c);
            v0 += bb.x; v1 += bb.y; v2 += bb.z; v3 += bb.w;
            int i = c >> 2;
            float fq = exp2f(-(float)i * 0.41524101186092036f);
            float sn, cs;
            sincosf(fs * fq, &sn, &cs);
            float q0 = v0 * cs - v2 * sn, q1 = v2 * cs + v0 * sn;
            float k0 = v1 * cs - v3 * sn, k1 = v3 * cs + v1 * sn;
            *reinterpret_cast<float2*>(g_q + (size_t)grow * 64 + 2 * i) =
                make_float2(q0 * 0.125f, q1 * 0.125f);
            *reinterpret_cast<float2*>(g_k + (size_t)grow * 64 + 2 * i) =
                make_float2(k0, k1);
        } else if (c < 168) {
            int cc = c - 128;
            float4 bb = *reinterpret_cast<const float4*>(b2 + cc);
            int l0 = cc >> 1;
            size_t o = (size_t)(b * Lc + l0) * Sc + s;
            g_bn[o]      = (v0 + bb.x) * 0.5f;
            g_bm[o]      = (v1 + bb.y) * 0.5f;
            g_bn[o + Sc] = (v2 + bb.z) * 0.5f;
            g_bm[o + Sc] = (v3 + bb.w) * 0.5f;
        }
    }
}

// ---------------- kernel 4: all output tiles (compute + constant paths) ------
__global__ void __launch_bounds__(256) phase2full_kernel(
    const int* __restrict__ am, float* __restrict__ out)
{
    __shared__ float qT[64][68];
    __shared__ float kT[64][68];
    __shared__ int   mMs[64], mNs[64];

    const size_t PROB_OFF = (size_t)Bc * Lc * Sc * Sc;
    int b = blockIdx.y;
    int tm = blockIdx.x >> 3, tn = blockIdx.x & 7;
    int tid = threadIdx.x;
    int m0 = tm * 64, n0 = tn * 64;

    if (tid < 64) {
        mMs[tid] = am[b * Sc + m0 + tid];
        mNs[tid] = am[b * Sc + n0 + tid];
    }

    if (tm > tn) {
        __syncthreads();
        float4 lv[4];
        int rowv[4], pv_[4];
        #pragma unroll
        for (int t = 0; t < 4; t++) {
            int idx = tid + t * 256;
            int row = idx >> 4, p = idx & 15;
            rowv[t] = row; pv_[t] = p;
            int mmv = mMs[row];
            lv[t].x = (mmv && mNs[p * 4 + 0]) ? -NEGF : -2.0f * NEGF;
            lv[t].y = (mmv && mNs[p * 4 + 1]) ? -NEGF : -2.0f * NEGF;
            lv[t].z = (mmv && mNs[p * 4 + 2]) ? -NEGF : -2.0f * NEGF;
            lv[t].w = (mmv && mNs[p * 4 + 3]) ? -NEGF : -2.0f * NEGF;
        }
        float4 z4 = make_float4(0.f, 0.f, 0.f, 0.f);
        size_t base = (((size_t)(b * Lc)) * Sc + m0) * (size_t)Sc + n0;
        for (int l = 0; l < Lc; l++) {
            #pragma unroll
            for (int t = 0; t < 4; t++) {
                size_t o = base + (size_t)rowv[t] * Sc + pv_[t] * 4;
                __stcs(reinterpret_cast<float4*>(out + o), lv[t]);
                __stcs(reinterpret_cast<float4*>(out + PROB_OFF + o), z4);
            }
            base += (size_t)Sc * Sc;
        }
        return;
    }

    const float* qb = g_q + (size_t)b * Sc * 64;
    const float* kb = g_k + (size_t)b * Sc * 64;
    #pragma unroll
    for (int t = 0; t < 16; t++) {
        int idx = tid + t * 256;
        int r = idx >> 6, kk = idx & 63;
        qT[kk][r] = qb[(size_t)(m0 + r) * 64 + kk];
        kT[kk][r] = kb[(size_t)(n0 + r) * 64 + kk];
    }
    __syncthreads();

    int tx = tid & 15, ty = tid >> 4;
    int nl = tx * 4, ml = ty * 4;

    ull acc2[4][2];
    #pragma unroll
    for (int i = 0; i < 4; i++) { acc2[i][0] = 0ull; acc2[i][1] = 0ull; }

    #pragma unroll 4
    for (int kk = 0; kk < 64; kk++) {
        float4 qv = *reinterpret_cast<const float4*>(&qT[kk][ml]);
        float4 kv = *reinterpret_cast<const float4*>(&kT[kk][nl]);
        ull k01 = pack2(kv.x, kv.y);
        ull k23 = pack2(kv.z, kv.w);
        ull q0 = bcast2(qv.x), q1 = bcast2(qv.y), q2 = bcast2(qv.z), q3 = bcast2(qv.w);
        acc2[0][0] = fma2(q0, k01, acc2[0][0]); acc2[0][1] = fma2(q0, k23, acc2[0][1]);
        acc2[1][0] = fma2(q1, k01, acc2[1][0]); acc2[1][1] = fma2(q1, k23, acc2[1][1]);
        acc2[2][0] = fma2(q2, k01, acc2[2][0]); acc2[2][1] = fma2(q2, k23, acc2[2][1]);
        acc2[3][0] = fma2(q3, k01, acc2[3][0]); acc2[3][1] = fma2(q3, k23, acc2[3][1]);
    }

    int mm[4], mn[4];
    #pragma unroll
    for (int i = 0; i < 4; i++) mm[i] = mMs[ml + i];
    #pragma unroll
    for (int j = 0; j < 4; j++) mn[j] = mNs[nl + j];

    float* probs = out + PROB_OFF;
    int gm0 = m0 + ml, gn0 = n0 + nl;
    size_t rowbase = (((size_t)(b * Lc)) * Sc + gm0) * (size_t)Sc + gn0;

    const float* bn_ptr = g_bn + (size_t)b * Lc * Sc + n0 + nl;
    const float* bm_ptr = g_bm + (size_t)b * Lc * Sc + m0 + ml;

    float4 bn_cur = __ldg(reinterpret_cast<const float4*>(bn_ptr));
    float4 bm_cur = __ldg(reinterpret_cast<const float4*>(bm_ptr));

    for (int l = 0; l < Lc; l++) {
        float4 bn_nxt, bm_nxt;
        if (l < Lc - 1) {
            bn_nxt = __ldg(reinterpret_cast<const float4*>(bn_ptr + (size_t)(l + 1) * Sc));
            bm_nxt = __ldg(reinterpret_cast<const float4*>(bm_ptr + (size_t)(l + 1) * Sc));
        }
        ull bn01 = pack2(bn_cur.x, bn_cur.y);
        ull bn23 = pack2(bn_cur.z, bn_cur.w);
        float bmv[4] = {bm_cur.x, bm_cur.y, bm_cur.z, bm_cur.w};
        #pragma unroll
        for (int i = 0; i < 4; i++) {
            int gm = gm0 + i;
            ull bm2 = bcast2(bmv[i]);
            ull v01 = add2(add2(acc2[i][0], bn01), bm2);
            ull v23 = add2(add2(acc2[i][1], bn23), bm2);
            float v[4];
            unpack2(v01, v[0], v[1]);
            unpack2(v23, v[2], v[3]);
            float lv[4], pv[4];
            #pragma unroll
            for (int j = 0; j < 4; j++) {
                float xv = (mm[i] && mn[j]) ? v[j] : -NEGF;
                if (gm > gn0 + j) xv -= NEGF;
                lv[j] = xv;
                pv[j] = fast_sigmoid(xv);
            }
            size_t o = rowbase + (size_t)i * Sc;
            __stcs(reinterpret_cast<float4*>(out + o),
                   make_float4(lv[0], lv[1], lv[2], lv[3]));
            __stcs(reinterpret_cast<float4*>(probs + o),
                   make_float4(pv[0], pv[1], pv[2], pv[3]));
        }
        bn_cur = bn_nxt;
        bm_cur = bm_nxt;
        rowbase += (size_t)Sc * Sc;
    }
}

// ---------------- launcher ----------------
extern "C" void kernel_launch(void* const* d_in, const int* in_sizes, int n_in,
                              void* d_out, int out_size) {
    (void)in_sizes; (void)n_in; (void)out_size;
    const float* x  = (const float*)d_in[0];
    const int*   am = (const int*)  d_in[1];
    const float* w1 = (const float*)d_in[2];
    const float* b1 = (const float*)d_in[3];
    const float* w2 = (const float*)d_in[4];
    const float* b2 = (const float*)d_in[5];
    float* out = (float*)d_out;

    static int smem_set = 0;
    if (!smem_set) {
        cudaFuncSetAttribute(gemm_kernel,
                             cudaFuncAttributeMaxDynamicSharedMemorySize, GEMM_SMEM);
        smem_set = 1;
    }

    split_x_kernel<<<3072, 256>>>(x);
    split_w_kernel<<<72, 256>>>(w1, w2);
    gemm_kernel<<<128, 256, GEMM_SMEM>>>(b1, b2);
    dim3 g2(64, 16);
    phase2full_kernel<<<g2, 256>>>(am, out);
}

// round 12
// speedup vs baseline: 2.2463x; 1.0592x over previous
#include <cuda_runtime.h>
#include <cuda_bf16.h>
#include <cstdint>

#define Bc 16
#define Sc 512
#define Dc 768
#define Lc 20
#define NEGF 1000000000000.0f

typedef unsigned long long ull;
typedef unsigned int u32;

// ---------------- scratch (no allocation allowed) ----------------
__device__ float g_q[Bc * Sc * 64];        // RoPE'd q, pre-scaled by 1/8 (exact)
__device__ float g_k[Bc * Sc * 64];
__device__ float g_bn[Bc * Lc * Sc];       // dense[b,2l,n]/2
__device__ float g_bm[Bc * Lc * Sc];       // dense[b,2l+1,m]/2
// row-major bf16 split B = W^T [192][768]
__device__ __nv_bfloat16 gB_h[192 * 768];
__device__ __nv_bfloat16 gB_l[192 * 768];

// ---------------- helpers ----------------
__device__ __forceinline__ ull fma2(ull a, ull b, ull c) {
    ull d; asm("fma.rn.f32x2 %0, %1, %2, %3;" : "=l"(d) : "l"(a), "l"(b), "l"(c)); return d;
}
__device__ __forceinline__ ull add2(ull a, ull b) {
    ull d; asm("add.rn.f32x2 %0, %1, %2;" : "=l"(d) : "l"(a), "l"(b)); return d;
}
__device__ __forceinline__ ull bcast2(float w) {
    ull d; u32 u = __float_as_uint(w);
    asm("mov.b64 %0, {%1, %1};" : "=l"(d) : "r"(u)); return d;
}
__device__ __forceinline__ ull pack2(float lo, float hi) {
    ull d; asm("mov.b64 %0, {%1, %2};" : "=l"(d) : "f"(lo), "f"(hi)); return d;
}
__device__ __forceinline__ void unpack2(ull v, float& lo, float& hi) {
    asm("mov.b64 {%0, %1}, %2;" : "=f"(lo), "=f"(hi) : "l"(v));
}
__device__ __forceinline__ float fast_sigmoid(float v) {
    float t; asm("tanh.approx.f32 %0, %1;" : "=f"(t) : "f"(v * 0.5f));
    return fmaf(t, 0.5f, 0.5f);
}
__device__ __forceinline__ u32 smem_u32_of(const void* p) {
    u32 a; asm("{ .reg .u64 t; cvta.to.shared.u64 t, %1; cvt.u32.u64 %0, t; }" : "=r"(a) : "l"(p));
    return a;
}
__device__ __forceinline__ void ldm4(u32* r, u32 addr) {
    asm volatile("ldmatrix.sync.aligned.m8n8.x4.shared.b16 {%0,%1,%2,%3}, [%4];"
        : "=r"(r[0]), "=r"(r[1]), "=r"(r[2]), "=r"(r[3]) : "r"(addr));
}
__device__ __forceinline__ void mma_bf16(float* d, const u32* a, const u32* b) {
    asm volatile("mma.sync.aligned.m16n8k16.row.col.f32.bf16.bf16.f32 "
        "{%0,%1,%2,%3}, {%4,%5,%6,%7}, {%8,%9}, {%0,%1,%2,%3};"
        : "+f"(d[0]), "+f"(d[1]), "+f"(d[2]), "+f"(d[3])
        : "r"(a[0]), "r"(a[1]), "r"(a[2]), "r"(a[3]), "r"(b[0]), "r"(b[1]));
}
__device__ __forceinline__ u32 split_pair(float a, float b, u32& lw) {
    __nv_bfloat16 h0 = __float2bfloat16_rn(a);
    __nv_bfloat16 h1 = __float2bfloat16_rn(b);
    __nv_bfloat16 l0 = __float2bfloat16_rn(a - __bfloat162float(h0));
    __nv_bfloat16 l1 = __float2bfloat16_rn(b - __bfloat162float(h1));
    lw = (u32)__bfloat16_as_ushort(l0) | ((u32)__bfloat16_as_ushort(l1) << 16);
    return (u32)__bfloat16_as_ushort(h0) | ((u32)__bfloat16_as_ushort(h1) << 16);
}

// ---------------- kernel 1: split W^T [192][768] into bf16 hi/lo -------------
__global__ void __launch_bounds__(256) split_w_kernel(
    const float* __restrict__ w1, const float* __restrict__ w2) {
    int idx = blockIdx.x * 256 + threadIdx.x;          // 18432 = 192*96 uint4
    int r = idx / 96, kg = idx % 96;
    u32 hw[4], lw[4];
    #pragma unroll
    for (int j = 0; j < 4; j++) {
        float va, vb;
        int k = kg * 8 + 2 * j;
        if (r < 128)      { va = w1[(size_t)k * 128 + r]; vb = w1[(size_t)(k+1) * 128 + r]; }
        else if (r < 168) { va = w2[(size_t)k * 40 + (r-128)]; vb = w2[(size_t)(k+1) * 40 + (r-128)]; }
        else              { va = 0.f; vb = 0.f; }
        hw[j] = split_pair(va, vb, lw[j]);
    }
    reinterpret_cast<uint4*>(gB_h)[idx] = make_uint4(hw[0], hw[1], hw[2], hw[3]);
    reinterpret_cast<uint4*>(gB_l)[idx] = make_uint4(lw[0], lw[1], lw[2], lw[3]);
}

// ---------------- kernel 2 (mega): HMMA GEMM blocks 0..127 || const writers --
// gemm smem rows padded to 72 bf16 (144 B) for conflict-free ldmatrix.
#define AH_OFF 0
#define AL_OFF 9216
#define BH_OFF 18432
#define BL_OFF 46080
#define GEMM_SMEM 73728      // >= max(tiles 73728, D 64*196*4=50176)

__global__ void __launch_bounds__(256) mega_kernel(
    const float* __restrict__ x, const int* __restrict__ am,
    const float* __restrict__ b1, const float* __restrict__ b2,
    float* __restrict__ out)
{
    extern __shared__ char smem[];
    int tid = threadIdx.x;

    if (blockIdx.x >= 128) {
        // ---------------- constant writer: tile tm>tn fully below diagonal ----
        const size_t PROB_OFF = (size_t)Bc * Lc * Sc * Sc;
        int* mMs = reinterpret_cast<int*>(smem);
        int* mNs = mMs + 64;
        int f = blockIdx.x - 128;            // 0..447
        int b = f / 28, p = f % 28;
        int tm = 1;
        while (p >= tm) { p -= tm; tm++; }   // tm 1..7, tn = p < tm
        int tn = p;
        int m0 = tm * 64, n0 = tn * 64;
        if (tid < 64) {
            mMs[tid] = am[b * Sc + m0 + tid];
            mNs[tid] = am[b * Sc + n0 + tid];
        }
        __syncthreads();
        float4 lv[4];
        int rowv[4], pv_[4];
        #pragma unroll
        for (int t = 0; t < 4; t++) {
            int idx = tid + t * 256;          // 1024 = 64 rows x 16 float4
            int row = idx >> 4, pp = idx & 15;
            rowv[t] = row; pv_[t] = pp;
            int mmv = mMs[row];
            lv[t].x = (mmv && mNs[pp * 4 + 0]) ? -NEGF : -2.0f * NEGF;
            lv[t].y = (mmv && mNs[pp * 4 + 1]) ? -NEGF : -2.0f * NEGF;
            lv[t].z = (mmv && mNs[pp * 4 + 2]) ? -NEGF : -2.0f * NEGF;
            lv[t].w = (mmv && mNs[pp * 4 + 3]) ? -NEGF : -2.0f * NEGF;
        }
        float4 z4 = make_float4(0.f, 0.f, 0.f, 0.f);
        size_t base = (((size_t)(b * Lc)) * Sc + m0) * (size_t)Sc + n0;
        for (int l = 0; l < Lc; l++) {
            #pragma unroll
            for (int t = 0; t < 4; t++) {
                size_t o = base + (size_t)rowv[t] * Sc + pv_[t] * 4;
                __stcs(reinterpret_cast<float4*>(out + o), lv[t]);
                __stcs(reinterpret_cast<float4*>(out + PROB_OFF + o), z4);
            }
            base += (size_t)Sc * Sc;
        }
        return;
    }

    // ---------------- GEMM path (rowTile = blockIdx.x) ------------------------
    u32 smem_u = smem_u32_of(smem);
    int wid = tid >> 5, lane = tid & 31;
    int rowTile = blockIdx.x;              // M block: rows rowTile*64 .. +63
    int wm = wid & 3, wn = wid >> 2;

    float acc[12][4];
    #pragma unroll
    for (int j = 0; j < 12; j++)
        #pragma unroll
        for (int q = 0; q < 4; q++) acc[j][q] = 0.f;

    int rr = lane & 7, qq = lane >> 3;
    u32 aoff = (u32)((rr + (qq & 1) * 8) * 144 + (qq >> 1) * 16);
    u32 boff = (u32)((rr + (qq >> 1) * 8) * 144 + (qq & 1) * 16);
    u32 aBaseH = smem_u + AH_OFF + wm * 16 * 144 + aoff;
    u32 aBaseL = smem_u + AL_OFF + wm * 16 * 144 + aoff;
    u32 bBaseH = smem_u + BH_OFF + wn * 96 * 144 + boff;
    u32 bBaseL = smem_u + BL_OFF + wn * 96 * 144 + boff;

    const uint4* srcBh = reinterpret_cast<const uint4*>(gB_h);
    const uint4* srcBl = reinterpret_cast<const uint4*>(gB_l);

    for (int kt = 0; kt < 12; kt++) {
        if (kt) __syncthreads();
        // A: read x fp32 directly, split in-register, store bf16 h/l to smem
        #pragma unroll
        for (int t = 0; t < 4; t++) {
            int idx = tid + t * 256;           // 1024 = 64 rows x 16 float4
            int r = idx >> 4, c4 = idx & 15;
            float4 v = *reinterpret_cast<const float4*>(
                x + (size_t)(rowTile * 64 + r) * Dc + kt * 64 + c4 * 4);
            u32 l0, l1;
            u32 h0 = split_pair(v.x, v.y, l0);
            u32 h1 = split_pair(v.z, v.w, l1);
            *reinterpret_cast<uint2*>(smem + AH_OFF + r * 144 + c4 * 8) = make_uint2(h0, h1);
            *reinterpret_cast<uint2*>(smem + AL_OFF + r * 144 + c4 * 8) = make_uint2(l0, l1);
        }
        // B: 192 rows x 8 uint4 from pre-split global
        #pragma unroll
        for (int t = 0; t < 6; t++) {
            int idx = tid + t * 256;
            int r = idx >> 3, c8 = idx & 7;
            size_t gi = (size_t)r * 96 + kt * 8 + c8;
            *reinterpret_cast<uint4*>(smem + BH_OFF + r * 144 + c8 * 16) = srcBh[gi];
            *reinterpret_cast<uint4*>(smem + BL_OFF + r * 144 + c8 * 16) = srcBl[gi];
        }
        __syncthreads();

        #pragma unroll
        for (int ks = 0; ks < 4; ks++) {
            u32 ah[4], al[4];
            ldm4(ah, aBaseH + ks * 32);
            ldm4(al, aBaseL + ks * 32);
            #pragma unroll
            for (int g = 0; g < 6; g++) {
                u32 bh[4], bl[4];
                ldm4(bh, bBaseH + g * 2304 + ks * 32);   // 16 rows * 144B
                ldm4(bl, bBaseL + g * 2304 + ks * 32);
                mma_bf16(acc[2*g],     ah, bh);
                mma_bf16(acc[2*g + 1], ah, bh + 2);
                mma_bf16(acc[2*g],     ah, bl);
                mma_bf16(acc[2*g + 1], ah, bl + 2);
                mma_bf16(acc[2*g],     al, bh);
                mma_bf16(acc[2*g + 1], al, bh + 2);
            }
        }
    }

    // dump accumulators to smem D[64][196] f32
    __syncthreads();
    float* Ds = reinterpret_cast<float*>(smem);
    {
        int mrow = wm * 16 + (lane >> 2);
        int ncol0 = wn * 96 + (lane & 3) * 2;
        #pragma unroll
        for (int j = 0; j < 12; j++) {
            int n = ncol0 + j * 8;
            *reinterpret_cast<float2*>(&Ds[mrow * 196 + n])       = make_float2(acc[j][0], acc[j][1]);
            *reinterpret_cast<float2*>(&Ds[(mrow + 8) * 196 + n]) = make_float2(acc[j][2], acc[j][3]);
        }
    }
    __syncthreads();

    // epilogue: bias + RoPE + scatter (each thread: 1 row, 48 cols)
    int row_l = (wid & 1) * 32 + lane;
    int colbase = (wid >> 1) * 48;
    int grow = rowTile * 64 + row_l;
    int b = grow >> 9, s = grow & 511;
    float fs = (float)s;

    #pragma unroll
    for (int g = 0; g < 12; g++) {
        int c = colbase + g * 4;
        float4 vv = *reinterpret_cast<const float4*>(&Ds[row_l * 196 + c]);
        float v0 = vv.x, v1 = vv.y, v2 = vv.z, v3 = vv.w;
        if (c < 128) {
            float4 bb = *reinterpret_cast<const float4*>(b1 + c);
            v0 += bb.x; v1 += bb.y; v2 += bb.z; v3 += bb.w;
            int i = c >> 2;
            float fq = exp2f(-(float)i * 0.41524101186092036f);
            float sn, cs;
            sincosf(fs * fq, &sn, &cs);
            float q0 = v0 * cs - v2 * sn, q1 = v2 * cs + v0 * sn;
            float k0 = v1 * cs - v3 * sn, k1 = v3 * cs + v1 * sn;
            *reinterpret_cast<float2*>(g_q + (size_t)grow * 64 + 2 * i) =
                make_float2(q0 * 0.125f, q1 * 0.125f);
            *reinterpret_cast<float2*>(g_k + (size_t)grow * 64 + 2 * i) =
                make_float2(k0, k1);
        } else if (c < 168) {
            int cc = c - 128;
            float4 bb = *reinterpret_cast<const float4*>(b2 + cc);
            int l0 = cc >> 1;
            size_t o = (size_t)(b * Lc + l0) * Sc + s;
            g_bn[o]      = (v0 + bb.x) * 0.5f;
            g_bm[o]      = (v1 + bb.y) * 0.5f;
            g_bn[o + Sc] = (v2 + bb.z) * 0.5f;
            g_bm[o + Sc] = (v3 + bb.w) * 0.5f;
        }
    }
}

// ---------------- kernel 3: compute tiles only (tm <= tn), all 20 L ----------
__global__ void __launch_bounds__(256, 4) phase2_kernel(
    const int* __restrict__ am, float* __restrict__ out)
{
    __shared__ float qT[64][68];
    __shared__ float kT[64][68];
    __shared__ int   mMs[64], mNs[64];

    const size_t PROB_OFF = (size_t)Bc * Lc * Sc * Sc;
    int b = blockIdx.y;
    int tmv = 0, tt = blockIdx.x;                 // 36 upper-tri tiles
    while (tt >= 8 - tmv) { tt -= 8 - tmv; tmv++; }
    int tnv = tmv + tt;

    int tid = threadIdx.x;
    int m0 = tmv * 64, n0 = tnv * 64;
    const float* qb = g_q + (size_t)b * Sc * 64;
    const float* kb = g_k + (size_t)b * Sc * 64;

    #pragma unroll
    for (int t = 0; t < 16; t++) {
        int idx = tid + t * 256;
        int r = idx >> 6, kk = idx & 63;
        qT[kk][r] = qb[(size_t)(m0 + r) * 64 + kk];
        kT[kk][r] = kb[(size_t)(n0 + r) * 64 + kk];
    }
    if (tid < 64) {
        mMs[tid] = am[b * Sc + m0 + tid];
        mNs[tid] = am[b * Sc + n0 + tid];
    }
    __syncthreads();

    int tx = tid & 15, ty = tid >> 4;
    int nl = tx * 4, ml = ty * 4;

    ull acc2[4][2];
    #pragma unroll
    for (int i = 0; i < 4; i++) { acc2[i][0] = 0ull; acc2[i][1] = 0ull; }

    #pragma unroll 4
    for (int kk = 0; kk < 64; kk++) {
        float4 qv = *reinterpret_cast<const float4*>(&qT[kk][ml]);
        float4 kv = *reinterpret_cast<const float4*>(&kT[kk][nl]);
        ull k01 = pack2(kv.x, kv.y);
        ull k23 = pack2(kv.z, kv.w);
        ull q0 = bcast2(qv.x), q1 = bcast2(qv.y), q2 = bcast2(qv.z), q3 = bcast2(qv.w);
        acc2[0][0] = fma2(q0, k01, acc2[0][0]); acc2[0][1] = fma2(q0, k23, acc2[0][1]);
        acc2[1][0] = fma2(q1, k01, acc2[1][0]); acc2[1][1] = fma2(q1, k23, acc2[1][1]);
        acc2[2][0] = fma2(q2, k01, acc2[2][0]); acc2[2][1] = fma2(q2, k23, acc2[2][1]);
        acc2[3][0] = fma2(q3, k01, acc2[3][0]); acc2[3][1] = fma2(q3, k23, acc2[3][1]);
    }

    int mm[4], mn[4];
    #pragma unroll
    for (int i = 0; i < 4; i++) mm[i] = mMs[ml + i];
    #pragma unroll
    for (int j = 0; j < 4; j++) mn[j] = mNs[nl + j];

    float* probs = out + PROB_OFF;
    int gm0 = m0 + ml, gn0 = n0 + nl;
    size_t rowbase = (((size_t)(b * Lc)) * Sc + gm0) * (size_t)Sc + gn0;

    const float* bn_ptr = g_bn + (size_t)b * Lc * Sc + n0 + nl;
    const float* bm_ptr = g_bm + (size_t)b * Lc * Sc + m0 + ml;

    float4 bn_cur = __ldg(reinterpret_cast<const float4*>(bn_ptr));
    float4 bm_cur = __ldg(reinterpret_cast<const float4*>(bm_ptr));

    for (int l = 0; l < Lc; l++) {
        float4 bn_nxt, bm_nxt;
        if (l < Lc - 1) {
            bn_nxt = __ldg(reinterpret_cast<const float4*>(bn_ptr + (size_t)(l + 1) * Sc));
            bm_nxt = __ldg(reinterpret_cast<const float4*>(bm_ptr + (size_t)(l + 1) * Sc));
        }
        ull bn01 = pack2(bn_cur.x, bn_cur.y);
        ull bn23 = pack2(bn_cur.z, bn_cur.w);
        float bmv[4] = {bm_cur.x, bm_cur.y, bm_cur.z, bm_cur.w};
        #pragma unroll
        for (int i = 0; i < 4; i++) {
            int gm = gm0 + i;
            ull bm2 = bcast2(bmv[i]);
            ull v01 = add2(add2(acc2[i][0], bn01), bm2);
            ull v23 = add2(add2(acc2[i][1], bn23), bm2);
            float v[4];
            unpack2(v01, v[0], v[1]);
            unpack2(v23, v[2], v[3]);
            float lv[4], pv[4];
            #pragma unroll
            for (int j = 0; j < 4; j++) {
                float xv = (mm[i] && mn[j]) ? v[j] : -NEGF;
                if (gm > gn0 + j) xv -= NEGF;
                lv[j] = xv;
                pv[j] = fast_sigmoid(xv);
            }
            size_t o = rowbase + (size_t)i * Sc;
            __stcs(reinterpret_cast<float4*>(out + o),
                   make_float4(lv[0], lv[1], lv[2], lv[3]));
            __stcs(reinterpret_cast<float4*>(probs + o),
                   make_float4(pv[0], pv[1], pv[2], pv[3]));
        }
        bn_cur = bn_nxt;
        bm_cur = bm_nxt;
        rowbase += (size_t)Sc * Sc;
    }
}

// ---------------- launcher ----------------
extern "C" void kernel_launch(void* const* d_in, const int* in_sizes, int n_in,
                              void* d_out, int out_size) {
    (void)in_sizes; (void)n_in; (void)out_size;
    const float* x  = (const float*)d_in[0];
    const int*   am = (const int*)  d_in[1];
    const float* w1 = (const float*)d_in[2];
    const float* b1 = (const float*)d_in[3];
    const float* w2 = (const float*)d_in[4];
    const float* b2 = (const float*)d_in[5];
    float* out = (float*)d_out;

    static int smem_set = 0;
    if (!smem_set) {
        cudaFuncSetAttribute(mega_kernel,
                             cudaFuncAttributeMaxDynamicSharedMemorySize, GEMM_SMEM);
        smem_set = 1;
    }

    split_w_kernel<<<72, 256>>>(w1, w2);
    mega_kernel<<<576, 256, GEMM_SMEM>>>(x, am, b1, b2, out);
    dim3 g2(36, 16);
    phase2_kernel<<<g2, 256>>>(am, out);
}

// round 13
// speedup vs baseline: 2.2467x; 1.0002x over previous
#include <cuda_runtime.h>
#include <cuda_bf16.h>
#include <cstdint>

#define Bc 16
#define Sc 512
#define Dc 768
#define Lc 20
#define NEGF 1000000000000.0f

typedef unsigned long long ull;
typedef unsigned int u32;

// ---------------- scratch (no allocation allowed) ----------------
__device__ float g_q[Bc * Sc * 64];        // RoPE'd q, pre-scaled by 1/8 (exact)
__device__ float g_k[Bc * Sc * 64];
__device__ float g_bn[Bc * Lc * Sc];       // dense[b,2l,n]/2
__device__ float g_bm[Bc * Lc * Sc];       // dense[b,2l+1,m]/2
__device__ __nv_bfloat16 gB_h[192 * 768];  // split W^T
__device__ __nv_bfloat16 gB_l[192 * 768];
__device__ int g_cnt[Bc];                  // per-batch gemm completion counters

// ---------------- helpers ----------------
__device__ __forceinline__ ull fma2(ull a, ull b, ull c) {
    ull d; asm("fma.rn.f32x2 %0, %1, %2, %3;" : "=l"(d) : "l"(a), "l"(b), "l"(c)); return d;
}
__device__ __forceinline__ ull add2(ull a, ull b) {
    ull d; asm("add.rn.f32x2 %0, %1, %2;" : "=l"(d) : "l"(a), "l"(b)); return d;
}
__device__ __forceinline__ ull bcast2(float w) {
    ull d; u32 u = __float_as_uint(w);
    asm("mov.b64 %0, {%1, %1};" : "=l"(d) : "r"(u)); return d;
}
__device__ __forceinline__ ull pack2(float lo, float hi) {
    ull d; asm("mov.b64 %0, {%1, %2};" : "=l"(d) : "f"(lo), "f"(hi)); return d;
}
__device__ __forceinline__ void unpack2(ull v, float& lo, float& hi) {
    asm("mov.b64 {%0, %1}, %2;" : "=f"(lo), "=f"(hi) : "l"(v));
}
__device__ __forceinline__ float fast_sigmoid(float v) {
    float t; asm("tanh.approx.f32 %0, %1;" : "=f"(t) : "f"(v * 0.5f));
    return fmaf(t, 0.5f, 0.5f);
}
__device__ __forceinline__ u32 smem_u32_of(const void* p) {
    u32 a; asm("{ .reg .u64 t; cvta.to.shared.u64 t, %1; cvt.u32.u64 %0, t; }" : "=r"(a) : "l"(p));
    return a;
}
__device__ __forceinline__ void ldm4(u32* r, u32 addr) {
    asm volatile("ldmatrix.sync.aligned.m8n8.x4.shared.b16 {%0,%1,%2,%3}, [%4];"
        : "=r"(r[0]), "=r"(r[1]), "=r"(r[2]), "=r"(r[3]) : "r"(addr));
}
__device__ __forceinline__ void mma_bf16(float* d, const u32* a, const u32* b) {
    asm volatile("mma.sync.aligned.m16n8k16.row.col.f32.bf16.bf16.f32 "
        "{%0,%1,%2,%3}, {%4,%5,%6,%7}, {%8,%9}, {%0,%1,%2,%3};"
        : "+f"(d[0]), "+f"(d[1]), "+f"(d[2]), "+f"(d[3])
        : "r"(a[0]), "r"(a[1]), "r"(a[2]), "r"(a[3]), "r"(b[0]), "r"(b[1]));
}
__device__ __forceinline__ u32 split_pair(float a, float b, u32& lw) {
    __nv_bfloat16 h0 = __float2bfloat16_rn(a);
    __nv_bfloat16 h1 = __float2bfloat16_rn(b);
    __nv_bfloat16 l0 = __float2bfloat16_rn(a - __bfloat162float(h0));
    __nv_bfloat16 l1 = __float2bfloat16_rn(b - __bfloat162float(h1));
    lw = (u32)__bfloat16_as_ushort(l0) | ((u32)__bfloat16_as_ushort(l1) << 16);
    return (u32)__bfloat16_as_ushort(h0) | ((u32)__bfloat16_as_ushort(h1) << 16);
}

// ---------------- shared writer body: const tile (tm>tn), one f --------------
template <typename SM>
__device__ __forceinline__ void writer_body(
    int f, int tid, const int* __restrict__ am, float* __restrict__ out,
    SM* mMs, SM* mNs)
{
    const size_t PROB_OFF = (size_t)Bc * Lc * Sc * Sc;
    int b = f / 28, p = f % 28;
    int tm = 1;
    while (p >= tm) { p -= tm; tm++; }   // tm 1..7, tn = p < tm
    int tn = p;
    int m0 = tm * 64, n0 = tn * 64;
    if (tid < 64) {
        mMs[tid] = am[b * Sc + m0 + tid];
        mNs[tid] = am[b * Sc + n0 + tid];
    }
    __syncthreads();
    float4 lv[4];
    int rowv[4], pv_[4];
    #pragma unroll
    for (int t = 0; t < 4; t++) {
        int idx = tid + t * 256;          // 1024 = 64 rows x 16 float4
        int row = idx >> 4, pp = idx & 15;
        rowv[t] = row; pv_[t] = pp;
        int mmv = mMs[row];
        lv[t].x = (mmv && mNs[pp * 4 + 0]) ? -NEGF : -2.0f * NEGF;
        lv[t].y = (mmv && mNs[pp * 4 + 1]) ? -NEGF : -2.0f * NEGF;
        lv[t].z = (mmv && mNs[pp * 4 + 2]) ? -NEGF : -2.0f * NEGF;
        lv[t].w = (mmv && mNs[pp * 4 + 3]) ? -NEGF : -2.0f * NEGF;
    }
    float4 z4 = make_float4(0.f, 0.f, 0.f, 0.f);
    size_t base = (((size_t)(b * Lc)) * Sc + m0) * (size_t)Sc + n0;
    for (int l = 0; l < Lc; l++) {
        #pragma unroll
        for (int t = 0; t < 4; t++) {
            size_t o = base + (size_t)rowv[t] * Sc + pv_[t] * 4;
            __stcs(reinterpret_cast<float4*>(out + o), lv[t]);
            __stcs(reinterpret_cast<float4*>(out + PROB_OFF + o), z4);
        }
        base += (size_t)Sc * Sc;
    }
}

// ---------------- kernel 1 (prep): split W + counters + 64 writer tiles ------
__global__ void __launch_bounds__(256) prep_kernel(
    const float* __restrict__ w1, const float* __restrict__ w2,
    const int* __restrict__ am, float* __restrict__ out)
{
    int tid = threadIdx.x;
    if (blockIdx.x == 0 && tid < Bc) g_cnt[tid] = 0;

    if (blockIdx.x < 72) {
        // split W^T [192][768] into bf16 hi/lo
        int idx = blockIdx.x * 256 + tid;              // 18432 = 192*96 uint4
        int r = idx / 96, kg = idx % 96;
        u32 hw[4], lw[4];
        #pragma unroll
        for (int j = 0; j < 4; j++) {
            float va, vb;
            int k = kg * 8 + 2 * j;
            if (r < 128)      { va = w1[(size_t)k * 128 + r]; vb = w1[(size_t)(k+1) * 128 + r]; }
            else if (r < 168) { va = w2[(size_t)k * 40 + (r-128)]; vb = w2[(size_t)(k+1) * 40 + (r-128)]; }
            else              { va = 0.f; vb = 0.f; }
            hw[j] = split_pair(va, vb, lw[j]);
        }
        reinterpret_cast<uint4*>(gB_h)[idx] = make_uint4(hw[0], hw[1], hw[2], hw[3]);
        reinterpret_cast<uint4*>(gB_l)[idx] = make_uint4(lw[0], lw[1], lw[2], lw[3]);
    } else {
        // writer tiles f = 0..63
        __shared__ int mMs[64], mNs[64];
        writer_body(blockIdx.x - 72, tid, am, out, mMs, mNs);
    }
}

// ---------------- kernel 2 (mega): gemm || writers || phase2 -----------------
// blocks 0..127: HMMA GEMM (rowTile), signal g_cnt[batch]
// blocks 128..511: writer tiles f = 64..447
// blocks 512..1087: phase2 compute tiles, spin on g_cnt[b] == 8
#define AH_OFF 0
#define AL_OFF 9216
#define BH_OFF 18432
#define BL_OFF 46080
#define GEMM_SMEM 73728      // >= max(tiles 73728, D 64*196*4, phase2 35328)

__global__ void __launch_bounds__(256) mega_kernel(
    const float* __restrict__ x, const int* __restrict__ am,
    const float* __restrict__ b1, const float* __restrict__ b2,
    float* __restrict__ out)
{
    extern __shared__ char smem[];
    int tid = threadIdx.x;
    const size_t PROB_OFF = (size_t)Bc * Lc * Sc * Sc;

    if (blockIdx.x >= 128 && blockIdx.x < 512) {
        // ---------------- constant writer ----------------
        int* mMs = reinterpret_cast<int*>(smem);
        int* mNs = mMs + 64;
        writer_body(64 + (int)blockIdx.x - 128, tid, am, out, mMs, mNs);
        return;
    }

    if (blockIdx.x >= 512) {
        // ---------------- phase2 compute tile (tm <= tn), all 20 L ------------
        int pidx = blockIdx.x - 512;
        int b = pidx / 36, tt = pidx % 36;
        int tmv = 0;
        while (tt >= 8 - tmv) { tt -= 8 - tmv; tmv++; }
        int tnv = tmv + tt;
        int m0 = tmv * 64, n0 = tnv * 64;

        float (*qT)[68] = reinterpret_cast<float(*)[68]>(smem);
        float (*kT)[68] = reinterpret_cast<float(*)[68]>(smem + 17408);
        int* mMs = reinterpret_cast<int*>(smem + 34816);
        int* mNs = mMs + 64;

        // wait for this batch's 8 gemm blocks
        if (tid == 0) {
            volatile int* c = g_cnt + b;
            while (*c < 8) __nanosleep(200);
        }
        __syncthreads();
        __threadfence();

        const float* qb = g_q + (size_t)b * Sc * 64;
        const float* kb = g_k + (size_t)b * Sc * 64;
        #pragma unroll
        for (int t = 0; t < 16; t++) {
            int idx = tid + t * 256;
            int r = idx >> 6, kk = idx & 63;
            qT[kk][r] = qb[(size_t)(m0 + r) * 64 + kk];
            kT[kk][r] = kb[(size_t)(n0 + r) * 64 + kk];
        }
        if (tid < 64) {
            mMs[tid] = am[b * Sc + m0 + tid];
            mNs[tid] = am[b * Sc + n0 + tid];
        }
        __syncthreads();

        int tx = tid & 15, ty = tid >> 4;
        int nl = tx * 4, ml = ty * 4;

        ull acc2[4][2];
        #pragma unroll
        for (int i = 0; i < 4; i++) { acc2[i][0] = 0ull; acc2[i][1] = 0ull; }

        #pragma unroll 4
        for (int kk = 0; kk < 64; kk++) {
            float4 qv = *reinterpret_cast<const float4*>(&qT[kk][ml]);
            float4 kv = *reinterpret_cast<const float4*>(&kT[kk][nl]);
            ull k01 = pack2(kv.x, kv.y);
            ull k23 = pack2(kv.z, kv.w);
            ull q0 = bcast2(qv.x), q1 = bcast2(qv.y), q2 = bcast2(qv.z), q3 = bcast2(qv.w);
            acc2[0][0] = fma2(q0, k01, acc2[0][0]); acc2[0][1] = fma2(q0, k23, acc2[0][1]);
            acc2[1][0] = fma2(q1, k01, acc2[1][0]); acc2[1][1] = fma2(q1, k23, acc2[1][1]);
            acc2[2][0] = fma2(q2, k01, acc2[2][0]); acc2[2][1] = fma2(q2, k23, acc2[2][1]);
            acc2[3][0] = fma2(q3, k01, acc2[3][0]); acc2[3][1] = fma2(q3, k23, acc2[3][1]);
        }

        int mm[4], mn[4];
        #pragma unroll
        for (int i = 0; i < 4; i++) mm[i] = mMs[ml + i];
        #pragma unroll
        for (int j = 0; j < 4; j++) mn[j] = mNs[nl + j];

        float* probs = out + PROB_OFF;
        int gm0 = m0 + ml, gn0 = n0 + nl;
        size_t rowbase = (((size_t)(b * Lc)) * Sc + gm0) * (size_t)Sc + gn0;

        const float* bn_ptr = g_bn + (size_t)b * Lc * Sc + n0 + nl;
        const float* bm_ptr = g_bm + (size_t)b * Lc * Sc + m0 + ml;

        float4 bn_cur = __ldg(reinterpret_cast<const float4*>(bn_ptr));
        float4 bm_cur = __ldg(reinterpret_cast<const float4*>(bm_ptr));

        for (int l = 0; l < Lc; l++) {
            float4 bn_nxt, bm_nxt;
            if (l < Lc - 1) {
                bn_nxt = __ldg(reinterpret_cast<const float4*>(bn_ptr + (size_t)(l + 1) * Sc));
                bm_nxt = __ldg(reinterpret_cast<const float4*>(bm_ptr + (size_t)(l + 1) * Sc));
            }
            ull bn01 = pack2(bn_cur.x, bn_cur.y);
            ull bn23 = pack2(bn_cur.z, bn_cur.w);
            float bmv[4] = {bm_cur.x, bm_cur.y, bm_cur.z, bm_cur.w};
            #pragma unroll
            for (int i = 0; i < 4; i++) {
                int gm = gm0 + i;
                ull bm2 = bcast2(bmv[i]);
                ull v01 = add2(add2(acc2[i][0], bn01), bm2);
                ull v23 = add2(add2(acc2[i][1], bn23), bm2);
                float v[4];
                unpack2(v01, v[0], v[1]);
                unpack2(v23, v[2], v[3]);
                float lv[4], pv[4];
                #pragma unroll
                for (int j = 0; j < 4; j++) {
                    float xv = (mm[i] && mn[j]) ? v[j] : -NEGF;
                    if (gm > gn0 + j) xv -= NEGF;
                    lv[j] = xv;
                    pv[j] = fast_sigmoid(xv);
                }
                size_t o = rowbase + (size_t)i * Sc;
                __stcs(reinterpret_cast<float4*>(out + o),
                       make_float4(lv[0], lv[1], lv[2], lv[3]));
                __stcs(reinterpret_cast<float4*>(probs + o),
                       make_float4(pv[0], pv[1], pv[2], pv[3]));
            }
            bn_cur = bn_nxt;
            bm_cur = bm_nxt;
            rowbase += (size_t)Sc * Sc;
        }
        return;
    }

    // ---------------- GEMM path (rowTile = blockIdx.x, 0..127) ----------------
    u32 smem_u = smem_u32_of(smem);
    int wid = tid >> 5, lane = tid & 31;
    int rowTile = blockIdx.x;
    int wm = wid & 3, wn = wid >> 2;

    float acc[12][4];
    #pragma unroll
    for (int j = 0; j < 12; j++)
        #pragma unroll
        for (int q = 0; q < 4; q++) acc[j][q] = 0.f;

    int rr = lane & 7, qq = lane >> 3;
    u32 aoff = (u32)((rr + (qq & 1) * 8) * 144 + (qq >> 1) * 16);
    u32 boff = (u32)((rr + (qq >> 1) * 8) * 144 + (qq & 1) * 16);
    u32 aBaseH = smem_u + AH_OFF + wm * 16 * 144 + aoff;
    u32 aBaseL = smem_u + AL_OFF + wm * 16 * 144 + aoff;
    u32 bBaseH = smem_u + BH_OFF + wn * 96 * 144 + boff;
    u32 bBaseL = smem_u + BL_OFF + wn * 96 * 144 + boff;

    const uint4* srcBh = reinterpret_cast<const uint4*>(gB_h);
    const uint4* srcBl = reinterpret_cast<const uint4*>(gB_l);

    for (int kt = 0; kt < 12; kt++) {
        if (kt) __syncthreads();
        #pragma unroll
        for (int t = 0; t < 4; t++) {
            int idx = tid + t * 256;           // 1024 = 64 rows x 16 float4
            int r = idx >> 4, c4 = idx & 15;
            float4 v = *reinterpret_cast<const float4*>(
                x + (size_t)(rowTile * 64 + r) * Dc + kt * 64 + c4 * 4);
            u32 l0, l1;
            u32 h0 = split_pair(v.x, v.y, l0);
            u32 h1 = split_pair(v.z, v.w, l1);
            *reinterpret_cast<uint2*>(smem + AH_OFF + r * 144 + c4 * 8) = make_uint2(h0, h1);
            *reinterpret_cast<uint2*>(smem + AL_OFF + r * 144 + c4 * 8) = make_uint2(l0, l1);
        }
        #pragma unroll
        for (int t = 0; t < 6; t++) {
            int idx = tid + t * 256;
            int r = idx >> 3, c8 = idx & 7;
            size_t gi = (size_t)r * 96 + kt * 8 + c8;
            *reinterpret_cast<uint4*>(smem + BH_OFF + r * 144 + c8 * 16) = srcBh[gi];
            *reinterpret_cast<uint4*>(smem + BL_OFF + r * 144 + c8 * 16) = srcBl[gi];
        }
        __syncthreads();

        #pragma unroll
        for (int ks = 0; ks < 4; ks++) {
            u32 ah[4], al[4];
            ldm4(ah, aBaseH + ks * 32);
            ldm4(al, aBaseL + ks * 32);
            #pragma unroll
            for (int g = 0; g < 6; g++) {
                u32 bh[4], bl[4];
                ldm4(bh, bBaseH + g * 2304 + ks * 32);   // 16 rows * 144B
                ldm4(bl, bBaseL + g * 2304 + ks * 32);
                mma_bf16(acc[2*g],     ah, bh);
                mma_bf16(acc[2*g + 1], ah, bh + 2);
                mma_bf16(acc[2*g],     ah, bl);
                mma_bf16(acc[2*g + 1], ah, bl + 2);
                mma_bf16(acc[2*g],     al, bh);
                mma_bf16(acc[2*g + 1], al, bh + 2);
            }
        }
    }

    // dump accumulators to smem D[64][196] f32
    __syncthreads();
    float* Ds = reinterpret_cast<float*>(smem);
    {
        int mrow = wm * 16 + (lane >> 2);
        int ncol0 = wn * 96 + (lane & 3) * 2;
        #pragma unroll
        for (int j = 0; j < 12; j++) {
            int n = ncol0 + j * 8;
            *reinterpret_cast<float2*>(&Ds[mrow * 196 + n])       = make_float2(acc[j][0], acc[j][1]);
            *reinterpret_cast<float2*>(&Ds[(mrow + 8) * 196 + n]) = make_float2(acc[j][2], acc[j][3]);
        }
    }
    __syncthreads();

    // epilogue: bias + RoPE + scatter (each thread: 1 row, 48 cols)
    int row_l = (wid & 1) * 32 + lane;
    int colbase = (wid >> 1) * 48;
    int grow = rowTile * 64 + row_l;
    int b = grow >> 9, s = grow & 511;
    float fs = (float)s;

    #pragma unroll
    for (int g = 0; g < 12; g++) {
        int c = colbase + g * 4;
        float4 vv = *reinterpret_cast<const float4*>(&Ds[row_l * 196 + c]);
        float v0 = vv.x, v1 = vv.y, v2 = vv.z, v3 = vv.w;
        if (c < 128) {
            float4 bb = *reinterpret_cast<const float4*>(b1 + c);
            v0 += bb.x; v1 += bb.y; v2 += bb.z; v3 += bb.w;
            int i = c >> 2;
            float fq = exp2f(-(float)i * 0.41524101186092036f);
            float sn, cs;
            sincosf(fs * fq, &sn, &cs);
            float q0 = v0 * cs - v2 * sn, q1 = v2 * cs + v0 * sn;
            float k0 = v1 * cs - v3 * sn, k1 = v3 * cs + v1 * sn;
            *reinterpret_cast<float2*>(g_q + (size_t)grow * 64 + 2 * i) =
                make_float2(q0 * 0.125f, q1 * 0.125f);
            *reinterpret_cast<float2*>(g_k + (size_t)grow * 64 + 2 * i) =
                make_float2(k0, k1);
        } else if (c < 168) {
            int cc = c - 128;
            float4 bb = *reinterpret_cast<const float4*>(b2 + cc);
            int l0 = cc >> 1;
            size_t o = (size_t)(b * Lc + l0) * Sc + s;
            g_bn[o]      = (v0 + bb.x) * 0.5f;
            g_bm[o]      = (v1 + bb.y) * 0.5f;
            g_bn[o + Sc] = (v2 + bb.z) * 0.5f;
            g_bm[o + Sc] = (v3 + bb.w) * 0.5f;
        }
    }

    // signal completion for this batch
    __threadfence();
    __syncthreads();
    if (tid == 0) atomicAdd(&g_cnt[rowTile >> 3], 1);
}

// ---------------- launcher ----------------
extern "C" void kernel_launch(void* const* d_in, const int* in_sizes, int n_in,
                              void* d_out, int out_size) {
    (void)in_sizes; (void)n_in; (void)out_size;
    const float* x  = (const float*)d_in[0];
    const int*   am = (const int*)  d_in[1];
    const float* w1 = (const float*)d_in[2];
    const float* b1 = (const float*)d_in[3];
    const float* w2 = (const float*)d_in[4];
    const float* b2 = (const float*)d_in[5];
    float* out = (float*)d_out;

    static int smem_set = 0;
    if (!smem_set) {
        cudaFuncSetAttribute(mega_kernel,
                             cudaFuncAttributeMaxDynamicSharedMemorySize, GEMM_SMEM);
        smem_set = 1;
    }

    prep_kernel<<<136, 256>>>(w1, w2, am, out);
    mega_kernel<<<1088, 256, GEMM_SMEM>>>(x, am, b1, b2, out);
}